// round 4
// baseline (speedup 1.0000x reference)
#include <cuda_runtime.h>
#include <cstdint>

#define NFRAMES 8
#define SEQLEN  25
#define BSZ     256
#define DF      16384
#define LAMF    0.1f
#define INVLAM  10.0f
#define SCHUNK  5
#define NCHUNK  5
#define THREADS 256

// ---------- sm_103a packed fp32 FMA (no mov glue: 64-bit "l" operands) ----------
__device__ __forceinline__ unsigned long long ffma2(unsigned long long a,
                                                    unsigned long long b,
                                                    unsigned long long c) {
    unsigned long long d;
    asm("fma.rn.f32x2 %0, %1, %2, %3;" : "=l"(d) : "l"(a), "l"(b), "l"(c));
    return d;
}
__device__ __forceinline__ float pairsum(unsigned long long v) {
    float lo, hi;
    asm("mov.b64 {%0,%1}, %2;" : "=f"(lo), "=f"(hi) : "l"(v));
    return lo + hi;
}
// 5-step butterfly warp sum (redux.f32 does not exist on sm_103)
__device__ __forceinline__ float warp_sum(float v) {
    v += __shfl_xor_sync(0xffffffffu, v, 16);
    v += __shfl_xor_sync(0xffffffffu, v, 8);
    v += __shfl_xor_sync(0xffffffffu, v, 4);
    v += __shfl_xor_sync(0xffffffffu, v, 2);
    v += __shfl_xor_sync(0xffffffffu, v, 1);
    return v;
}

// ---------- normalized D accessor: D[r][c] = dot[i][j] * sninv[i] * tninv[j] ----------
template <bool TR>
__device__ __forceinline__ float getD(const float* __restrict__ d,
                                      const float* __restrict__ sn,
                                      const float* __restrict__ tn,
                                      int r, int c) {
    const int rr = TR ? c : r;   // support-frame index
    const int cc = TR ? r : c;   // target-frame index
    return d[rr * 8 + cc] * sn[rr] * tn[cc];
}

// stable pairwise lam*logsumexp
__device__ __forceinline__ float lsep(float a, float b) {
    float m = fmaxf(a, b);
    float d = fabsf(a - b);
    return fmaf(LAMF, log1pf(__expf(-d * INVLAM)), m);
}

// OTAM soft-DP on an 8x8 matrix (optionally transposed view)
template <bool TR>
__device__ float dp8(const float* __restrict__ dsh,
                     const float* __restrict__ sninv,
                     const float* __restrict__ tninv) {
    float prev[8];
#pragma unroll
    for (int r = 0; r < 8; r++) prev[r] = getD<TR>(dsh, sninv, tninv, r, 0);
#pragma unroll
    for (int c = 1; c < 8; c++) {
        float nw[8];
        nw[0] = prev[0] + getD<TR>(dsh, sninv, tninv, 0, c);
#pragma unroll
        for (int r = 1; r < 8; r++) {
            nw[r] = lsep(prev[r - 1], prev[r]) + getD<TR>(dsh, sninv, tninv, r, c);
        }
#pragma unroll
        for (int r = 0; r < 8; r++) prev[r] = nw[r];
    }
    float m = prev[0];
#pragma unroll
    for (int r = 1; r < 8; r++) m = fmaxf(m, prev[r]);
    float s = 0.0f;
#pragma unroll
    for (int r = 0; r < 8; r++) s += __expf((prev[r] - m) * INVLAM);
    return fmaf(LAMF, __logf(s), m);
}

__global__ void __launch_bounds__(THREADS, 2)
otam_kernel(const ulonglong2* __restrict__ sup,   // [25,256,16384] f32 viewed as ull2
            const ulonglong2* __restrict__ tgt,   // [256,16384]     f32 viewed as ull2
            float* __restrict__ out)              // [25,256]
{
    __shared__ float buf[8][9][8];   // [i][dot_j(0..7)|norm(8)][warp]
    __shared__ float dot_sh[64];
    __shared__ float sninv_sh[8];
    __shared__ float tninv_sh[8];

    const int t    = threadIdx.x;
    const int w    = t >> 5;
    const int lane = t & 31;
    const int b    = blockIdx.x;
    const int chunk = blockIdx.y;

    // ---- load target frames for this b into registers (8 frames x 8 floats/thread) ----
    const ulonglong2* tb = tgt + (size_t)b * (DF / 4);
    unsigned long long tva[8][4];
#pragma unroll
    for (int j = 0; j < 8; j++) {
        ulonglong2 a = tb[j * 512 + t];
        ulonglong2 c = tb[j * 512 + 256 + t];
        tva[j][0] = a.x; tva[j][1] = a.y; tva[j][2] = c.x; tva[j][3] = c.y;
    }
    // ---- target norms (once per block) ----
#pragma unroll
    for (int j = 0; j < 8; j++) {
        unsigned long long n2 = 0ull;
#pragma unroll
        for (int c = 0; c < 4; c++) n2 = ffma2(tva[j][c], tva[j][c], n2);
        float v = warp_sum(pairsum(n2));
        if (lane == 0) buf[0][j][w] = v;
    }
    __syncthreads();
    if (t < 8) {
        float s = 0.0f;
#pragma unroll
        for (int ww = 0; ww < 8; ww++) s += buf[0][t][ww];
        tninv_sh[t] = 1.0f / fmaxf(sqrtf(s), 1e-12f);
    }
    __syncthreads();

    // ---- main loop over this block's s values ----
    for (int ss = 0; ss < SCHUNK; ss++) {
        const int s = chunk * SCHUNK + ss;
        const ulonglong2* sb = sup + ((size_t)s * BSZ + b) * (DF / 4);

        ulonglong2 pa = sb[t];
        ulonglong2 pb = sb[256 + t];
#pragma unroll
        for (int i = 0; i < 8; i++) {
            const unsigned long long ca0 = pa.x, ca1 = pa.y, cb0 = pb.x, cb1 = pb.y;
            if (i < 7) {   // software prefetch next frame
                pa = sb[(i + 1) * 512 + t];
                pb = sb[(i + 1) * 512 + 256 + t];
            }
            unsigned long long acc[8];
#pragma unroll
            for (int j = 0; j < 8; j++) acc[j] = 0ull;
            unsigned long long n2 = 0ull;
            n2 = ffma2(ca0, ca0, n2);
            n2 = ffma2(ca1, ca1, n2);
            n2 = ffma2(cb0, cb0, n2);
            n2 = ffma2(cb1, cb1, n2);
#pragma unroll
            for (int j = 0; j < 8; j++) {
                acc[j] = ffma2(ca0, tva[j][0], acc[j]);
                acc[j] = ffma2(ca1, tva[j][1], acc[j]);
                acc[j] = ffma2(cb0, tva[j][2], acc[j]);
                acc[j] = ffma2(cb1, tva[j][3], acc[j]);
            }
            // warp reductions (9 values), one slot per warp in shared
            {
                float vn = warp_sum(pairsum(n2));
                if (lane == 0) buf[i][8][w] = vn;
            }
#pragma unroll
            for (int j = 0; j < 8; j++) {
                float vd = warp_sum(pairsum(acc[j]));
                if (lane == 0) buf[i][j][w] = vd;
            }
        }
        __syncthreads();
        // cross-warp finish: 72 values, one thread each
        if (t < 72) {
            const int i = t / 9, k = t % 9;
            float ssum = 0.0f;
#pragma unroll
            for (int ww = 0; ww < 8; ww++) ssum += buf[i][k][ww];
            if (k == 8) sninv_sh[i] = 1.0f / fmaxf(sqrtf(ssum), 1e-12f);
            else        dot_sh[i * 8 + k] = ssum;
        }
        __syncthreads();
        // tiny DP on one thread; overlaps with next s iteration of other warps
        if (t == 0) {
            float r0 = dp8<false>(dot_sh, sninv_sh, tninv_sh);
            float r1 = dp8<true >(dot_sh, sninv_sh, tninv_sh);
            out[s * BSZ + b] = 0.5f * (r0 + r1);
        }
    }
}

extern "C" void kernel_launch(void* const* d_in, const int* in_sizes, int n_in,
                              void* d_out, int out_size) {
    const ulonglong2* sup = (const ulonglong2*)d_in[0];  // support_vecs [25,256,16384] f32
    const ulonglong2* tgt = (const ulonglong2*)d_in[1];  // target_vec  [256,16384]    f32
    float* out = (float*)d_out;                           // [25,256] f32
    (void)in_sizes; (void)n_in; (void)out_size;

    dim3 grid(BSZ, NCHUNK);
    otam_kernel<<<grid, THREADS>>>(sup, tgt, out);
}

// round 8
// speedup vs baseline: 1.0490x; 1.0490x over previous
#include <cuda_runtime.h>
#include <cstdint>

#define NFRAMES 8
#define SEQLEN  25
#define BSZ     256
#define DF      16384
#define LAMF    0.1f
#define INVLAM  10.0f
#define SCHUNK  5
#define NCHUNK  5
#define THREADS 256

// ---------- sm_103a packed fp32 FMA ----------
__device__ __forceinline__ unsigned long long ffma2(unsigned long long a,
                                                    unsigned long long b,
                                                    unsigned long long c) {
    unsigned long long d;
    asm("fma.rn.f32x2 %0, %1, %2, %3;" : "=l"(d) : "l"(a), "l"(b), "l"(c));
    return d;
}
__device__ __forceinline__ float pairsum(unsigned long long v) {
    float lo, hi;
    asm("mov.b64 {%0,%1}, %2;" : "=f"(lo), "=f"(hi) : "l"(v));
    return lo + hi;
}
__device__ __forceinline__ float warp_sum(float v) {
    v += __shfl_xor_sync(0xffffffffu, v, 16);
    v += __shfl_xor_sync(0xffffffffu, v, 8);
    v += __shfl_xor_sync(0xffffffffu, v, 4);
    v += __shfl_xor_sync(0xffffffffu, v, 2);
    v += __shfl_xor_sync(0xffffffffu, v, 1);
    return v;
}

// Multi-value warp reduction: 8 independent values in 9 SHFLs.
// Afterwards v[0] at lane l holds the full warp sum of value bitrev3(l&7),
// where bitrev3: 0,4,2,6,1,5,3,7.
__device__ __forceinline__ void reduce8(float v[8], unsigned lane) {
#pragma unroll
    for (int k = 0; k < 4; k++) {
        float send = (lane & 1) ? v[k] : v[k + 4];
        float keep = (lane & 1) ? v[k + 4] : v[k];
        v[k] = keep + __shfl_xor_sync(0xffffffffu, send, 1);
    }
#pragma unroll
    for (int k = 0; k < 2; k++) {
        float send = (lane & 2) ? v[k] : v[k + 2];
        float keep = (lane & 2) ? v[k + 2] : v[k];
        v[k] = keep + __shfl_xor_sync(0xffffffffu, send, 2);
    }
    {
        float send = (lane & 4) ? v[0] : v[1];
        float keep = (lane & 4) ? v[1] : v[0];
        v[0] = keep + __shfl_xor_sync(0xffffffffu, send, 4);
    }
    v[0] += __shfl_xor_sync(0xffffffffu, v[0], 8);
    v[0] += __shfl_xor_sync(0xffffffffu, v[0], 16);
}
__device__ __forceinline__ int bitrev3(int l) {
    return ((l & 1) << 2) | (l & 2) | ((l & 4) >> 2);
}

// ---------- normalized D accessor ----------
template <bool TR>
__device__ __forceinline__ float getD(const float* __restrict__ d,
                                      const float* __restrict__ sn,
                                      const float* __restrict__ tn,
                                      int r, int c) {
    const int rr = TR ? c : r;
    const int cc = TR ? r : c;
    return d[rr * 8 + cc] * sn[rr] * tn[cc];
}

__device__ __forceinline__ float lsep(float a, float b) {
    float m = fmaxf(a, b);
    float d = fabsf(a - b);
    return fmaf(LAMF, log1pf(__expf(-d * INVLAM)), m);
}

template <bool TR>
__device__ float dp8(const float* __restrict__ dsh,
                     const float* __restrict__ sninv,
                     const float* __restrict__ tninv) {
    float prev[8];
#pragma unroll
    for (int r = 0; r < 8; r++) prev[r] = getD<TR>(dsh, sninv, tninv, r, 0);
#pragma unroll
    for (int c = 1; c < 8; c++) {
        float nw[8];
        nw[0] = prev[0] + getD<TR>(dsh, sninv, tninv, 0, c);
#pragma unroll
        for (int r = 1; r < 8; r++)
            nw[r] = lsep(prev[r - 1], prev[r]) + getD<TR>(dsh, sninv, tninv, r, c);
#pragma unroll
        for (int r = 0; r < 8; r++) prev[r] = nw[r];
    }
    float m = prev[0];
#pragma unroll
    for (int r = 1; r < 8; r++) m = fmaxf(m, prev[r]);
    float s = 0.0f;
#pragma unroll
    for (int r = 0; r < 8; r++) s += __expf((prev[r] - m) * INVLAM);
    return fmaf(LAMF, __logf(s), m);
}

__global__ void __launch_bounds__(THREADS, 2)
otam_kernel(const ulonglong2* __restrict__ sup,   // [25,256,16384] f32 as ull2
            const ulonglong2* __restrict__ tgt,   // [256,16384]    f32 as ull2
            float* __restrict__ out)              // [25,256]
{
    __shared__ float bufD[8][8][8];   // [frame i][dot j][warp]
    __shared__ float bufN[8][8];      // [frame i][warp]
    __shared__ float dot_sh[64];
    __shared__ float sninv_sh[8];
    __shared__ float tninv_sh[8];

    const int t     = threadIdx.x;
    const int w     = t >> 5;
    const unsigned lane = t & 31;
    const int b     = blockIdx.x;
    const int chunk = blockIdx.y;

    // ---- target frames for this b: 8 frames x 8 floats per thread, in registers ----
    const ulonglong2* tb = tgt + (size_t)b * (DF / 4);
    unsigned long long tva[8][4];
#pragma unroll
    for (int j = 0; j < 8; j++) {
        ulonglong2 a = tb[j * 512 + t];
        ulonglong2 c = tb[j * 512 + 256 + t];
        tva[j][0] = a.x; tva[j][1] = a.y; tva[j][2] = c.x; tva[j][3] = c.y;
    }
    // ---- target norms (once per block) ----
#pragma unroll
    for (int j = 0; j < 8; j++) {
        unsigned long long n2 = 0ull;
#pragma unroll
        for (int c = 0; c < 4; c++) n2 = ffma2(tva[j][c], tva[j][c], n2);
        float v = warp_sum(pairsum(n2));
        if (lane == 0) bufN[j][w] = v;
    }
    __syncthreads();
    if (t < 8) {
        float s = 0.0f;
#pragma unroll
        for (int ww = 0; ww < 8; ww++) s += bufN[t][ww];
        tninv_sh[t] = 1.0f / fmaxf(sqrtf(s), 1e-12f);
    }
    __syncthreads();

    // ---- main loop over this block's s values, 2-slot frame ring, distance-2 prefetch ----
    const size_t sstride = (size_t)BSZ * (DF / 4);
    const ulonglong2* sb = sup + ((size_t)(chunk * SCHUNK) * BSZ + b) * (DF / 4);

    ulonglong2 A0 = sb[t],       A1 = sb[256 + t];   // frame 0
    ulonglong2 B0 = sb[512 + t], B1 = sb[768 + t];   // frame 1

    for (int ss = 0; ss < SCHUNK; ss++) {
        const int s = chunk * SCHUNK + ss;
        const ulonglong2* nxt = (ss == SCHUNK - 1) ? sb : (sb + sstride);

        float nrm[8];
#pragma unroll
        for (int i = 0; i < 8; i++) {
            unsigned long long ca0, ca1, cb0, cb1;
            if ((i & 1) == 0) { ca0 = A0.x; ca1 = A0.y; cb0 = A1.x; cb1 = A1.y; }
            else              { ca0 = B0.x; ca1 = B0.y; cb0 = B1.x; cb1 = B1.y; }

            // prefetch frame i+2 of current s, or frame i-6 of next s, into same slot
            const ulonglong2* pf = (i < 6) ? (sb + (size_t)(i + 2) * 512)
                                           : (nxt + (size_t)(i - 6) * 512);
            if ((i & 1) == 0) { A0 = pf[t]; A1 = pf[256 + t]; }
            else              { B0 = pf[t]; B1 = pf[256 + t]; }

            unsigned long long acc[8];
#pragma unroll
            for (int j = 0; j < 8; j++) acc[j] = 0ull;
            unsigned long long n2 = 0ull;
            n2 = ffma2(ca0, ca0, n2);
            n2 = ffma2(ca1, ca1, n2);
            n2 = ffma2(cb0, cb0, n2);
            n2 = ffma2(cb1, cb1, n2);
#pragma unroll
            for (int j = 0; j < 8; j++) {
                acc[j] = ffma2(ca0, tva[j][0], acc[j]);
                acc[j] = ffma2(ca1, tva[j][1], acc[j]);
                acc[j] = ffma2(cb0, tva[j][2], acc[j]);
                acc[j] = ffma2(cb1, tva[j][3], acc[j]);
            }
            nrm[i] = pairsum(n2);
            float d[8];
#pragma unroll
            for (int j = 0; j < 8; j++) d[j] = pairsum(acc[j]);
            reduce8(d, lane);                         // 9 SHFLs for 8 dots
            if (lane < 8) bufD[i][bitrev3((int)lane)][w] = d[0];
        }
        // all 8 frame norms reduced at once: 9 SHFLs instead of 40
        reduce8(nrm, lane);
        if (lane < 8) bufN[bitrev3((int)lane)][w] = nrm[0];

        __syncthreads();
        if (t < 64) {
            const int i = t >> 3, j = t & 7;
            float ssum = 0.0f;
#pragma unroll
            for (int ww = 0; ww < 8; ww++) ssum += bufD[i][j][ww];
            dot_sh[i * 8 + j] = ssum;
        } else if (t < 72) {
            const int i = t - 64;
            float ssum = 0.0f;
#pragma unroll
            for (int ww = 0; ww < 8; ww++) ssum += bufN[i][ww];
            sninv_sh[i] = 1.0f / fmaxf(sqrtf(ssum), 1e-12f);
        }
        __syncthreads();
        if (t == 0) {
            float r0 = dp8<false>(dot_sh, sninv_sh, tninv_sh);
            float r1 = dp8<true >(dot_sh, sninv_sh, tninv_sh);
            out[s * BSZ + b] = 0.5f * (r0 + r1);
        }
        sb = nxt;
    }
}

extern "C" void kernel_launch(void* const* d_in, const int* in_sizes, int n_in,
                              void* d_out, int out_size) {
    const ulonglong2* sup = (const ulonglong2*)d_in[0];
    const ulonglong2* tgt = (const ulonglong2*)d_in[1];
    float* out = (float*)d_out;
    (void)in_sizes; (void)n_in; (void)out_size;

    dim3 grid(BSZ, NCHUNK);
    otam_kernel<<<grid, THREADS>>>(sup, tgt, out);
}

// round 10
// speedup vs baseline: 1.0597x; 1.0102x over previous
#include <cuda_runtime.h>
#include <cstdint>

#define NFRAMES 8
#define SEQLEN  25
#define BSZ     256
#define DF      16384
#define LAMF    0.1f
#define INVLAM  10.0f
#define SCHUNK  5
#define NCHUNK  5
#define THREADS 256
#define RING    12          // smem ring slots (frames), 8KB each
#define PF      9           // prefetch depth (frames in flight)
#define NFR_TOT (SCHUNK * NFRAMES)   // 40 frames streamed per CTA

// ---------- sm_103a packed fp32 FMA ----------
__device__ __forceinline__ unsigned long long ffma2(unsigned long long a,
                                                    unsigned long long b,
                                                    unsigned long long c) {
    unsigned long long d;
    asm("fma.rn.f32x2 %0, %1, %2, %3;" : "=l"(d) : "l"(a), "l"(b), "l"(c));
    return d;
}
__device__ __forceinline__ float pairsum(unsigned long long v) {
    float lo, hi;
    asm("mov.b64 {%0,%1}, %2;" : "=f"(lo), "=f"(hi) : "l"(v));
    return lo + hi;
}
__device__ __forceinline__ float warp_sum(float v) {
    v += __shfl_xor_sync(0xffffffffu, v, 16);
    v += __shfl_xor_sync(0xffffffffu, v, 8);
    v += __shfl_xor_sync(0xffffffffu, v, 4);
    v += __shfl_xor_sync(0xffffffffu, v, 2);
    v += __shfl_xor_sync(0xffffffffu, v, 1);
    return v;
}

// Multi-value warp reduction: 8 independent values in 9 SHFLs.
// Afterwards v[0] at lane l holds the full warp sum of value bitrev3(l&7).
__device__ __forceinline__ void reduce8(float v[8], unsigned lane) {
#pragma unroll
    for (int k = 0; k < 4; k++) {
        float send = (lane & 1) ? v[k] : v[k + 4];
        float keep = (lane & 1) ? v[k + 4] : v[k];
        v[k] = keep + __shfl_xor_sync(0xffffffffu, send, 1);
    }
#pragma unroll
    for (int k = 0; k < 2; k++) {
        float send = (lane & 2) ? v[k] : v[k + 2];
        float keep = (lane & 2) ? v[k + 2] : v[k];
        v[k] = keep + __shfl_xor_sync(0xffffffffu, send, 2);
    }
    {
        float send = (lane & 4) ? v[0] : v[1];
        float keep = (lane & 4) ? v[1] : v[0];
        v[0] = keep + __shfl_xor_sync(0xffffffffu, send, 4);
    }
    v[0] += __shfl_xor_sync(0xffffffffu, v[0], 8);
    v[0] += __shfl_xor_sync(0xffffffffu, v[0], 16);
}
__device__ __forceinline__ int bitrev3(int l) {
    return ((l & 1) << 2) | (l & 2) | ((l & 4) >> 2);
}

// ---------- cp.async helpers ----------
__device__ __forceinline__ void cp16(unsigned smem_addr, const void* gptr) {
    asm volatile("cp.async.cg.shared.global [%0], [%1], 16;\n"
                 :: "r"(smem_addr), "l"(gptr));
}
__device__ __forceinline__ void cp_commit() {
    asm volatile("cp.async.commit_group;\n");
}
template <int N>
__device__ __forceinline__ void cp_wait() {
    asm volatile("cp.async.wait_group %0;\n" :: "n"(N));
}

// ---------- normalized D accessor ----------
template <bool TR>
__device__ __forceinline__ float getD(const float* __restrict__ d,
                                      const float* __restrict__ sn,
                                      const float* __restrict__ tn,
                                      int r, int c) {
    const int rr = TR ? c : r;
    const int cc = TR ? r : c;
    return d[rr * 8 + cc] * sn[rr] * tn[cc];
}

__device__ __forceinline__ float lsep(float a, float b) {
    float m = fmaxf(a, b);
    float d = fabsf(a - b);
    return fmaf(LAMF, log1pf(__expf(-d * INVLAM)), m);
}

template <bool TR>
__device__ float dp8(const float* __restrict__ dsh,
                     const float* __restrict__ sninv,
                     const float* __restrict__ tninv) {
    float prev[8];
#pragma unroll
    for (int r = 0; r < 8; r++) prev[r] = getD<TR>(dsh, sninv, tninv, r, 0);
#pragma unroll
    for (int c = 1; c < 8; c++) {
        float nw[8];
        nw[0] = prev[0] + getD<TR>(dsh, sninv, tninv, 0, c);
#pragma unroll
        for (int r = 1; r < 8; r++)
            nw[r] = lsep(prev[r - 1], prev[r]) + getD<TR>(dsh, sninv, tninv, r, c);
#pragma unroll
        for (int r = 0; r < 8; r++) prev[r] = nw[r];
    }
    float m = prev[0];
#pragma unroll
    for (int r = 1; r < 8; r++) m = fmaxf(m, prev[r]);
    float s = 0.0f;
#pragma unroll
    for (int r = 0; r < 8; r++) s += __expf((prev[r] - m) * INVLAM);
    return fmaf(LAMF, __logf(s), m);
}

__global__ void __launch_bounds__(THREADS, 2)
otam_kernel(const ulonglong2* __restrict__ sup,   // [25,256,16384] f32 as ull2
            const ulonglong2* __restrict__ tgt,   // [256,16384]    f32 as ull2
            float* __restrict__ out)              // [25,256]
{
    // dynamic smem ring: [RING][2][256] x 16B = RING*8KB
    extern __shared__ ulonglong2 ring[];

    __shared__ float bufD[8][8][8];   // [frame i][dot j][warp]
    __shared__ float bufN[8][8];      // [frame i][warp]
    __shared__ float dot_sh[64];
    __shared__ float sninv_sh[8];
    __shared__ float tninv_sh[8];

    const int t     = threadIdx.x;
    const int w     = t >> 5;
    const unsigned lane = t & 31;
    const int b     = blockIdx.x;
    const int chunk = blockIdx.y;

    // per-thread smem destinations (2 float4s per frame slot)
    unsigned ring_base = (unsigned)__cvta_generic_to_shared(ring);

    // global base for this CTA's frame stream:
    // frame f (0..39): s_local = f>>3, i = f&7
    // addr (ull2 units): ((chunk*SCHUNK + s_local)*BSZ + b)*(DF/4) + i*512
    const ulonglong2* gbase = sup + ((size_t)(chunk * SCHUNK) * BSZ + b) * (DF / 4);
    const size_t sstride = (size_t)BSZ * (DF / 4);

    // ---- issue one frame's cp.asyncs (this thread's 32B only) ----
    auto issue = [&](int f) {
        const int sl = f >> 3, i = f & 7;
        const ulonglong2* src = gbase + (size_t)sl * sstride + (size_t)i * 512;
        const int slot = f % RING;
        unsigned d0 = ring_base + ((slot * 2 + 0) * 256 + t) * 16;
        unsigned d1 = ring_base + ((slot * 2 + 1) * 256 + t) * 16;
        cp16(d0, src + t);
        cp16(d1, src + 256 + t);
        cp_commit();
    };

    // ---- prologue: fill pipeline ----
#pragma unroll
    for (int f = 0; f < PF; f++) issue(f);

    // ---- target frames for this b: 8 frames x 8 floats per thread, registers ----
    const ulonglong2* tb = tgt + (size_t)b * (DF / 4);
    unsigned long long tva[8][4];
#pragma unroll
    for (int j = 0; j < 8; j++) {
        ulonglong2 a = tb[j * 512 + t];
        ulonglong2 c = tb[j * 512 + 256 + t];
        tva[j][0] = a.x; tva[j][1] = a.y; tva[j][2] = c.x; tva[j][3] = c.y;
    }
    // ---- target norms (once per block) ----
#pragma unroll
    for (int j = 0; j < 8; j++) {
        unsigned long long n2 = 0ull;
#pragma unroll
        for (int c = 0; c < 4; c++) n2 = ffma2(tva[j][c], tva[j][c], n2);
        float v = warp_sum(pairsum(n2));
        if (lane == 0) bufN[j][w] = v;
    }
    __syncthreads();
    if (t < 8) {
        float s = 0.0f;
#pragma unroll
        for (int ww = 0; ww < 8; ww++) s += bufN[t][ww];
        tninv_sh[t] = 1.0f / fmaxf(sqrtf(s), 1e-12f);
    }
    __syncthreads();

    // ---- main streaming loop: 5 s-values x 8 frames ----
    for (int ss = 0; ss < SCHUNK; ss++) {
        const int s = chunk * SCHUNK + ss;
        float nrm[8];
#pragma unroll
        for (int i = 0; i < 8; i++) {
            const int f = ss * 8 + i;
            cp_wait<PF - 1>();                 // frame f's data (this thread's) landed
            const int slot = f % RING;
            ulonglong2 A = ring[(slot * 2 + 0) * 256 + t];
            ulonglong2 B = ring[(slot * 2 + 1) * 256 + t];
            if (f + PF < NFR_TOT) issue(f + PF);   // keep pipeline full

            const unsigned long long ca0 = A.x, ca1 = A.y, cb0 = B.x, cb1 = B.y;
            unsigned long long acc[8];
#pragma unroll
            for (int j = 0; j < 8; j++) acc[j] = 0ull;
            unsigned long long n2 = 0ull;
            n2 = ffma2(ca0, ca0, n2);
            n2 = ffma2(ca1, ca1, n2);
            n2 = ffma2(cb0, cb0, n2);
            n2 = ffma2(cb1, cb1, n2);
#pragma unroll
            for (int j = 0; j < 8; j++) {
                acc[j] = ffma2(ca0, tva[j][0], acc[j]);
                acc[j] = ffma2(ca1, tva[j][1], acc[j]);
                acc[j] = ffma2(cb0, tva[j][2], acc[j]);
                acc[j] = ffma2(cb1, tva[j][3], acc[j]);
            }
            nrm[i] = pairsum(n2);
            float d[8];
#pragma unroll
            for (int j = 0; j < 8; j++) d[j] = pairsum(acc[j]);
            reduce8(d, lane);
            if (lane < 8) bufD[i][bitrev3((int)lane)][w] = d[0];
        }
        reduce8(nrm, lane);
        if (lane < 8) bufN[bitrev3((int)lane)][w] = nrm[0];

        __syncthreads();
        if (t < 64) {
            const int i = t >> 3, j = t & 7;
            float ssum = 0.0f;
#pragma unroll
            for (int ww = 0; ww < 8; ww++) ssum += bufD[i][j][ww];
            dot_sh[i * 8 + j] = ssum;
        } else if (t < 72) {
            const int i = t - 64;
            float ssum = 0.0f;
#pragma unroll
            for (int ww = 0; ww < 8; ww++) ssum += bufN[i][ww];
            sninv_sh[i] = 1.0f / fmaxf(sqrtf(ssum), 1e-12f);
        }
        __syncthreads();
        if (t == 0) {
            float r0 = dp8<false>(dot_sh, sninv_sh, tninv_sh);
            float r1 = dp8<true >(dot_sh, sninv_sh, tninv_sh);
            out[s * BSZ + b] = 0.5f * (r0 + r1);
        }
    }
}

extern "C" void kernel_launch(void* const* d_in, const int* in_sizes, int n_in,
                              void* d_out, int out_size) {
    const ulonglong2* sup = (const ulonglong2*)d_in[0];
    const ulonglong2* tgt = (const ulonglong2*)d_in[1];
    float* out = (float*)d_out;
    (void)in_sizes; (void)n_in; (void)out_size;

    const int smem_bytes = RING * 2 * 256 * 16;   // 96KB dynamic ring
    static bool attr_set = false;
    // idempotent attribute set (not a stream op; safe under graph capture)
    cudaFuncSetAttribute(otam_kernel, cudaFuncAttributeMaxDynamicSharedMemorySize,
                         smem_bytes);
    (void)attr_set;

    dim3 grid(BSZ, NCHUNK);
    otam_kernel<<<grid, THREADS, smem_bytes>>>(sup, tgt, out);
}

// round 11
// speedup vs baseline: 2.3579x; 2.2251x over previous
#include <cuda_runtime.h>
#include <cstdint>

#define NFRAMES 8
#define SEQLEN  25
#define BSZ     256
#define DF      16384
#define LAMF    0.1f
#define INVLAM  10.0f
#define SCHUNK  5
#define NCHUNK  5
#define THREADS 256
#define RING    12
#define PF      9
#define NFR_TOT (SCHUNK * NFRAMES)

// ---------- sm_103a packed fp32 FMA ----------
__device__ __forceinline__ unsigned long long ffma2(unsigned long long a,
                                                    unsigned long long b,
                                                    unsigned long long c) {
    unsigned long long d;
    asm("fma.rn.f32x2 %0, %1, %2, %3;" : "=l"(d) : "l"(a), "l"(b), "l"(c));
    return d;
}
__device__ __forceinline__ float pairsum(unsigned long long v) {
    float lo, hi;
    asm("mov.b64 {%0,%1}, %2;" : "=f"(lo), "=f"(hi) : "l"(v));
    return lo + hi;
}
__device__ __forceinline__ float warp_sum(float v) {
    v += __shfl_xor_sync(0xffffffffu, v, 16);
    v += __shfl_xor_sync(0xffffffffu, v, 8);
    v += __shfl_xor_sync(0xffffffffu, v, 4);
    v += __shfl_xor_sync(0xffffffffu, v, 2);
    v += __shfl_xor_sync(0xffffffffu, v, 1);
    return v;
}

// Truncated multi-value reduction: 8 values, 3 SHFL stages (7 SHFLs total).
// Afterwards v[0] at lane l = sum of value bitrev3(l&7) over l's aligned
// 8-lane group (4 groups per warp -> 32 partials per CTA-warp set).
__device__ __forceinline__ void reduce8_3(float v[8], unsigned lane) {
#pragma unroll
    for (int k = 0; k < 4; k++) {
        float send = (lane & 1) ? v[k] : v[k + 4];
        float keep = (lane & 1) ? v[k + 4] : v[k];
        v[k] = keep + __shfl_xor_sync(0xffffffffu, send, 1);
    }
#pragma unroll
    for (int k = 0; k < 2; k++) {
        float send = (lane & 2) ? v[k] : v[k + 2];
        float keep = (lane & 2) ? v[k + 2] : v[k];
        v[k] = keep + __shfl_xor_sync(0xffffffffu, send, 2);
    }
    {
        float send = (lane & 4) ? v[0] : v[1];
        float keep = (lane & 4) ? v[1] : v[0];
        v[0] = keep + __shfl_xor_sync(0xffffffffu, send, 4);
    }
}
__device__ __forceinline__ int bitrev3(int l) {
    return ((l & 1) << 2) | (l & 2) | ((l & 4) >> 2);
}

// ---------- cp.async helpers ----------
__device__ __forceinline__ void cp16(unsigned smem_addr, const void* gptr) {
    asm volatile("cp.async.cg.shared.global [%0], [%1], 16;\n"
                 :: "r"(smem_addr), "l"(gptr));
}
__device__ __forceinline__ void cp_commit() {
    asm volatile("cp.async.commit_group;\n");
}
template <int N>
__device__ __forceinline__ void cp_wait() {
    asm volatile("cp.async.wait_group %0;\n" :: "n"(N));
}

// fast stable pairwise lam*logsumexp (MUFU ex2/lg2; log1p error <= 2e-10*lam)
__device__ __forceinline__ float lsep(float a, float b) {
    float m = fmaxf(a, b);
    float d = fabsf(a - b);
    return fmaf(LAMF, __logf(1.0f + __expf(-d * INVLAM)), m);
}

// runtime-transposed OTAM soft-DP on the 8x8 matrix
__device__ float dp8r(const float* __restrict__ d,
                      const float* __restrict__ sn,
                      const float* __restrict__ tn, bool tr) {
    float prev[8];
#pragma unroll
    for (int r = 0; r < 8; r++) {
        int rr = tr ? 0 : r, cc = tr ? r : 0;
        prev[r] = d[rr * 8 + cc] * sn[rr] * tn[cc];
    }
#pragma unroll
    for (int c = 1; c < 8; c++) {
        float nw[8];
        {
            int rr = tr ? c : 0, cc = tr ? 0 : c;
            nw[0] = prev[0] + d[rr * 8 + cc] * sn[rr] * tn[cc];
        }
#pragma unroll
        for (int r = 1; r < 8; r++) {
            int rr = tr ? c : r, cc = tr ? r : c;
            nw[r] = lsep(prev[r - 1], prev[r]) + d[rr * 8 + cc] * sn[rr] * tn[cc];
        }
#pragma unroll
        for (int r = 0; r < 8; r++) prev[r] = nw[r];
    }
    float m = prev[0];
#pragma unroll
    for (int r = 1; r < 8; r++) m = fmaxf(m, prev[r]);
    float s = 0.0f;
#pragma unroll
    for (int r = 0; r < 8; r++) s += __expf((prev[r] - m) * INVLAM);
    return fmaf(LAMF, __logf(s), m);
}

__global__ void __launch_bounds__(THREADS, 2)
otam_kernel(const ulonglong2* __restrict__ sup,   // [25,256,16384] f32 as ull2
            const ulonglong2* __restrict__ tgt,   // [256,16384]    f32 as ull2
            float* __restrict__ out)              // [25,256]
{
    extern __shared__ ulonglong2 ring[];          // [RING][2][256] x 16B = 96KB

    // 72 rows (64 dots + 8 norms) x 32 partials, stride 36 for bank-free stores
    __shared__ __align__(16) float bufAll[72 * 36];
    __shared__ float dot_sh[64];
    __shared__ float sninv_sh[8];
    __shared__ float tninv_sh[8];

    const int t     = threadIdx.x;
    const int w     = t >> 5;
    const unsigned lane = t & 31;
    const int g     = (int)(lane >> 3);           // 8-lane group 0..3
    const int col32 = w * 4 + g;                  // partial slot 0..31
    const int b     = blockIdx.x;
    const int chunk = blockIdx.y;

    unsigned ring_base = (unsigned)__cvta_generic_to_shared(ring);
    const ulonglong2* gbase = sup + ((size_t)(chunk * SCHUNK) * BSZ + b) * (DF / 4);
    const size_t sstride = (size_t)BSZ * (DF / 4);

    auto issue = [&](int f) {   // always commits (empty groups keep wait math exact)
        if (f < NFR_TOT) {
            const int sl = f >> 3, i = f & 7;
            const ulonglong2* src = gbase + (size_t)sl * sstride + (size_t)i * 512;
            const int slot = f % RING;
            cp16(ring_base + ((slot * 2 + 0) * 256 + t) * 16, src + t);
            cp16(ring_base + ((slot * 2 + 1) * 256 + t) * 16, src + 256 + t);
        }
        cp_commit();
    };

#pragma unroll
    for (int f = 0; f < PF; f++) issue(f);

    // ---- target frames in registers: 8 frames x 8 floats/thread ----
    const ulonglong2* tb = tgt + (size_t)b * (DF / 4);
    unsigned long long tva[8][4];
#pragma unroll
    for (int j = 0; j < 8; j++) {
        ulonglong2 a = tb[j * 512 + t];
        ulonglong2 c = tb[j * 512 + 256 + t];
        tva[j][0] = a.x; tva[j][1] = a.y; tva[j][2] = c.x; tva[j][3] = c.y;
    }
    // ---- target norms (once per block; reuse bufAll as scratch) ----
#pragma unroll
    for (int j = 0; j < 8; j++) {
        unsigned long long n2 = 0ull;
#pragma unroll
        for (int c = 0; c < 4; c++) n2 = ffma2(tva[j][c], tva[j][c], n2);
        float v = warp_sum(pairsum(n2));
        if (lane == 0) bufAll[j * 36 + w] = v;
    }
    __syncthreads();
    if (t < 8) {
        float s = 0.0f;
#pragma unroll
        for (int ww = 0; ww < 8; ww++) s += bufAll[t * 36 + ww];
        tninv_sh[t] = 1.0f / fmaxf(sqrtf(s), 1e-12f);
    }
    __syncthreads();

    // ---- main streaming loop ----
    for (int ss = 0; ss < SCHUNK; ss++) {
        const int s = chunk * SCHUNK + ss;
        float nrm[8];
#pragma unroll
        for (int i = 0; i < 8; i++) {
            const int f = ss * 8 + i;
            cp_wait<PF - 1>();                       // group f complete (exact)
            const int slot = f % RING;
            ulonglong2 A = ring[(slot * 2 + 0) * 256 + t];
            ulonglong2 B = ring[(slot * 2 + 1) * 256 + t];
            issue(f + PF);

            const unsigned long long ca0 = A.x, ca1 = A.y, cb0 = B.x, cb1 = B.y;
            unsigned long long acc[8];
#pragma unroll
            for (int j = 0; j < 8; j++) acc[j] = 0ull;
            unsigned long long n2 = 0ull;
            n2 = ffma2(ca0, ca0, n2);
            n2 = ffma2(ca1, ca1, n2);
            n2 = ffma2(cb0, cb0, n2);
            n2 = ffma2(cb1, cb1, n2);
#pragma unroll
            for (int j = 0; j < 8; j++) {
                acc[j] = ffma2(ca0, tva[j][0], acc[j]);
                acc[j] = ffma2(ca1, tva[j][1], acc[j]);
                acc[j] = ffma2(cb0, tva[j][2], acc[j]);
                acc[j] = ffma2(cb1, tva[j][3], acc[j]);
            }
            nrm[i] = pairsum(n2);
            float d[8];
#pragma unroll
            for (int j = 0; j < 8; j++) d[j] = pairsum(acc[j]);
            reduce8_3(d, lane);                      // 3-stage, all 32 lanes store
            bufAll[(i * 8 + bitrev3((int)(lane & 7))) * 36 + col32] = d[0];
        }
        reduce8_3(nrm, lane);
        bufAll[(64 + bitrev3((int)(lane & 7))) * 36 + col32] = nrm[0];

        __syncthreads();
        if (t < 72) {                                // sum 32 partials per row
            const float4* p = (const float4*)(bufAll + t * 36);
            float ssum = 0.0f;
#pragma unroll
            for (int k = 0; k < 8; k++) {
                float4 v4 = p[k];
                ssum += (v4.x + v4.y) + (v4.z + v4.w);
            }
            if (t < 64) dot_sh[t] = ssum;
            else        sninv_sh[t - 64] = 1.0f / fmaxf(sqrtf(ssum), 1e-12f);
        }
        __syncthreads();
        if (w == 0) {                                // DP: warp-parallel, both views
            float r = dp8r(dot_sh, sninv_sh, tninv_sh, (lane & 1) != 0);
            float o = __shfl_xor_sync(0xffffffffu, r, 1);
            if (lane == 0) out[s * BSZ + b] = 0.5f * (r + o);
        }
    }
}

extern "C" void kernel_launch(void* const* d_in, const int* in_sizes, int n_in,
                              void* d_out, int out_size) {
    const ulonglong2* sup = (const ulonglong2*)d_in[0];
    const ulonglong2* tgt = (const ulonglong2*)d_in[1];
    float* out = (float*)d_out;
    (void)in_sizes; (void)n_in; (void)out_size;

    const int smem_bytes = RING * 2 * 256 * 16;   // 96KB dynamic ring
    cudaFuncSetAttribute(otam_kernel, cudaFuncAttributeMaxDynamicSharedMemorySize,
                         smem_bytes);

    dim3 grid(BSZ, NCHUNK);
    otam_kernel<<<grid, THREADS, smem_bytes>>>(sup, tgt, out);
}